// round 13
// baseline (speedup 1.0000x reference)
#include <cuda_runtime.h>
#include <cuda_bf16.h>
#include <cstdint>

// ---------------------------------------------------------------------------
// Problem constants
// ---------------------------------------------------------------------------
#define NPTS   32768
#define FCH    64
#define MSEL   8192
#define KNBR   64
#define HID    128
#define OUTC   128

// ---------------------------------------------------------------------------
// Scratch (device globals; no allocation allowed)
// ---------------------------------------------------------------------------
__device__ float g_selpos[MSEL * 3];
__device__ float g_hpre[NPTS * HID];
__device__ int   g_nbr[MSEL * KNBR];
__device__ int   g_ncnt[MSEL];

// spatial-sort scratch for FPS
#define NCELL 4096                                   // 16x16x16 Morton cells
__device__ int    g_ccnt[NCELL];
__device__ int    g_coff[NCELL];
__device__ float4 g_pxyz[NPTS];                      // x,y,z, orig-idx (bit-cast)

__device__ __forceinline__ float d2_exact(float dx, float dy, float dz) {
    // Match XLA: elementwise square then add-reduce, NO fma contraction.
    return __fadd_rn(__fadd_rn(__fmul_rn(dx, dx), __fmul_rn(dy, dy)),
                     __fmul_rn(dz, dz));
}

__device__ __forceinline__ int cell_of(float x, float y, float z) {
    int cx = min(15, max(0, (int)(x * 16.0f)));
    int cy = min(15, max(0, (int)(y * 16.0f)));
    int cz = min(15, max(0, (int)(z * 16.0f)));
    int code = 0;
#pragma unroll
    for (int b = 0; b < 4; b++) {
        code |= ((cx >> b) & 1) << (3 * b);
        code |= ((cy >> b) & 1) << (3 * b + 1);
        code |= ((cz >> b) & 1) << (3 * b + 2);
    }
    return code;
}

// ===========================================================================
// Prep: Morton-cell counting sort of points
// ===========================================================================
__global__ void zero_cells_kernel() {
    int i = blockIdx.x * blockDim.x + threadIdx.x;
    if (i < NCELL) g_ccnt[i] = 0;
}

__global__ void count_cells_kernel(const float* __restrict__ pos) {
    int i = blockIdx.x * blockDim.x + threadIdx.x;
    if (i < NPTS)
        atomicAdd(&g_ccnt[cell_of(pos[3 * i], pos[3 * i + 1], pos[3 * i + 2])], 1);
}

__global__ void __launch_bounds__(1024) scan_cells_kernel() {
    __shared__ int a[NCELL], b[NCELL];
    const int tid = threadIdx.x;
    for (int s = tid; s < NCELL; s += 1024) a[s] = g_ccnt[s];
    __syncthreads();
    int* src = a; int* dst = b;
    for (int off = 1; off < NCELL; off <<= 1) {
        for (int s = tid; s < NCELL; s += 1024)
            dst[s] = src[s] + ((s >= off) ? src[s - off] : 0);
        __syncthreads();
        int* t = src; src = dst; dst = t;
    }
    for (int s = tid; s < NCELL; s += 1024)
        g_coff[s] = (s ? src[s - 1] : 0);
}

__global__ void scatter_kernel(const float* __restrict__ pos) {
    int i = blockIdx.x * blockDim.x + threadIdx.x;
    if (i >= NPTS) return;
    float x = pos[3 * i], y = pos[3 * i + 1], z = pos[3 * i + 2];
    int slot = atomicAdd(&g_coff[cell_of(x, y, z)], 1);
    g_pxyz[slot] = make_float4(x, y, z, __int_as_float(i));
}

// ===========================================================================
// Stage A: FPS — SINGLE CTA, 1024 threads, 2 buckets (of 16 pts) per thread.
// min_d lives in 128KB dynamic SMEM (bank-conflict-free layout); positions
// reloaded from L2 only on the (rare) bucket rescans. No cluster traffic.
// ===========================================================================
#define F1_THREADS 1024
#define F1_BUCKETS 2048
#define F1_PTS     16

__global__ void __launch_bounds__(F1_THREADS, 1)
fps1_kernel(const float* __restrict__ pos)
{
    extern __shared__ float s_mind[];   // [F1_PTS][F1_BUCKETS] = 128KB
    __shared__ unsigned swv[32], swo[32];
    __shared__ float    swx[32], swy[32], swz[32];
    __shared__ float    s_w[3];

    const int tid  = threadIdx.x;
    const int lane = tid & 31;
    const int warp = tid >> 5;
    const float POS_INF = __int_as_float(0x7f800000);

    // --- per-thread bucket state (k = 0,1 -> bucket b = tid + k*1024) ---
    float bxmin[2], bxmax[2], bymin[2], bymax[2], bzmin[2], bzmax[2];
    float bv[2];        // cached bucket max-min-dist (candidate value)
    unsigned boi[2];    // candidate orig index
    float bcx[2], bcy[2], bcz[2];   // candidate position

#pragma unroll
    for (int k = 0; k < 2; k++) {
        const int b = tid + k * F1_THREADS;
        float xmn = POS_INF, xmx = -POS_INF;
        float ymn = POS_INF, ymx = -POS_INF;
        float zmn = POS_INF, zmx = -POS_INF;
#pragma unroll
        for (int j = 0; j < F1_PTS; j++) {
            float4 p = __ldg(&g_pxyz[b * F1_PTS + j]);
            xmn = fminf(xmn, p.x); xmx = fmaxf(xmx, p.x);
            ymn = fminf(ymn, p.y); ymx = fmaxf(ymx, p.y);
            zmn = fminf(zmn, p.z); zmx = fmaxf(zmx, p.z);
            s_mind[j * F1_BUCKETS + b] = POS_INF;
        }
        bxmin[k] = xmn; bxmax[k] = xmx;
        bymin[k] = ymn; bymax[k] = ymx;
        bzmin[k] = zmn; bzmax[k] = zmx;
        bv[k] = POS_INF;            // forces full rescan at i=1
        boi[k] = 0u;
        bcx[k] = 0.f; bcy[k] = 0.f; bcz[k] = 0.f;
    }

    float wx = pos[0], wy = pos[1], wz = pos[2];
    if (tid == 0) {
        g_selpos[0] = wx; g_selpos[1] = wy; g_selpos[2] = wz;
    }
    __syncthreads();

    for (int i = 1; i < MSEL; ++i) {
        // ---- per-bucket: prune-check, rescan if needed, keep cached candidate
#pragma unroll
        for (int k = 0; k < 2; k++) {
            // conservative (round-down) lower bound of d2(winner, bucket bbox)
            float gx = fmaxf(fmaxf(__fsub_rd(bxmin[k], wx), __fsub_rd(wx, bxmax[k])), 0.f);
            float gy = fmaxf(fmaxf(__fsub_rd(bymin[k], wy), __fsub_rd(wy, bymax[k])), 0.f);
            float gz = fmaxf(fmaxf(__fsub_rd(bzmin[k], wz), __fsub_rd(wz, bzmax[k])), 0.f);
            float lb = __fmul_rd(
                __fadd_rd(__fadd_rd(__fmul_rd(gx, gx), __fmul_rd(gy, gy)),
                          __fmul_rd(gz, gz)),
                0.999998f);

            if (lb < bv[k]) {     // bucket may change: exact rescan
                const int b = tid + k * F1_THREADS;
                float nbv = -1.0f; unsigned nboi = 0xffffffffu;
                float nx = 0.f, ny = 0.f, nz = 0.f;
#pragma unroll
                for (int j = 0; j < F1_PTS; j++) {
                    float4 p = __ldg(&g_pxyz[b * F1_PTS + j]);
                    float dx = p.x - wx, dy = p.y - wy, dz = p.z - wz;
                    float d2 = d2_exact(dx, dy, dz);
                    float m  = fminf(s_mind[j * F1_BUCKETS + b], d2);
                    s_mind[j * F1_BUCKETS + b] = m;
                    unsigned oj = (unsigned)__float_as_int(p.w);
                    bool better = (m > nbv) || (m == nbv && oj < nboi);
                    if (better) { nbv = m; nboi = oj; nx = p.x; ny = p.y; nz = p.z; }
                }
                bv[k] = nbv; boi[k] = nboi;
                bcx[k] = nx; bcy[k] = ny; bcz[k] = nz;
            }
        }

        // ---- thread candidate = better of its two buckets
        float    tv; unsigned to; float tx, ty, tz;
        bool sec = (bv[1] > bv[0]) || (bv[1] == bv[0] && boi[1] < boi[0]);
        if (sec) { tv = bv[1]; to = boi[1]; tx = bcx[1]; ty = bcy[1]; tz = bcz[1]; }
        else     { tv = bv[0]; to = boi[0]; tx = bcx[0]; ty = bcy[0]; tz = bcz[0]; }

        // ---- warp reduce: max value bits, then min orig idx among ties
        unsigned vbits = __float_as_uint(tv);       // tv >= 0 -> order-preserving
        unsigned vmax  = __reduce_max_sync(0xffffffffu, vbits);
        unsigned oc    = (vbits == vmax) ? to : 0xffffffffu;
        unsigned omin  = __reduce_min_sync(0xffffffffu, oc);
        unsigned ball  = __ballot_sync(0xffffffffu, oc == omin);
        int src = __ffs(ball) - 1;
        float kx = __shfl_sync(0xffffffffu, tx, src);
        float ky = __shfl_sync(0xffffffffu, ty, src);
        float kz = __shfl_sync(0xffffffffu, tz, src);
        if (lane == 0) {
            swv[warp] = vmax; swo[warp] = omin;
            swx[warp] = kx;   swy[warp] = ky;   swz[warp] = kz;
        }
        __syncthreads();

        // ---- warp 0 reduces the 32 warp candidates, publishes winner
        if (warp == 0) {
            unsigned v2 = swv[lane];
            unsigned o2 = swo[lane];
            unsigned vmax2 = __reduce_max_sync(0xffffffffu, v2);
            unsigned oc2   = (v2 == vmax2) ? o2 : 0xffffffffu;
            unsigned omin2 = __reduce_min_sync(0xffffffffu, oc2);
            unsigned b2    = __ballot_sync(0xffffffffu, oc2 == omin2);
            int s2 = __ffs(b2) - 1;
            float X = __shfl_sync(0xffffffffu, swx[lane], s2);
            float Y = __shfl_sync(0xffffffffu, swy[lane], s2);
            float Z = __shfl_sync(0xffffffffu, swz[lane], s2);
            if (lane == 0) {
                s_w[0] = X; s_w[1] = Y; s_w[2] = Z;
                g_selpos[3 * i]     = X;
                g_selpos[3 * i + 1] = Y;
                g_selpos[3 * i + 2] = Z;
            }
        }
        __syncthreads();
        wx = s_w[0]; wy = s_w[1]; wz = s_w[2];
    }
}

// ===========================================================================
// Stage C0: h_pre[j][ch] = b1[ch] + x[j,:]@W1[:64,ch] + pos[j,:]@W1[64:67,ch]
// ===========================================================================
__global__ void __launch_bounds__(128)
hpre_kernel(const float* __restrict__ x, const float* __restrict__ pos,
            const float* __restrict__ W1, const float* __restrict__ b1)
{
    const int t = threadIdx.x;
    float w1c[FCH + 3];
#pragma unroll
    for (int f = 0; f < FCH + 3; f++) w1c[f] = W1[f * HID + t];
    const float bb = b1[t];

    __shared__ float xs[FCH];
    __shared__ float ps[3];

    const int row0 = blockIdx.x * 64;
    for (int r = 0; r < 64; r++) {
        const int row = row0 + r;
        if (t < FCH) xs[t] = x[row * FCH + t];
        if (t < 3)   ps[t] = pos[row * 3 + t];
        __syncthreads();
        float acc = bb;
        acc = fmaf(ps[0], w1c[64], acc);
        acc = fmaf(ps[1], w1c[65], acc);
        acc = fmaf(ps[2], w1c[66], acc);
#pragma unroll
        for (int f = 0; f < FCH; f++) acc = fmaf(xs[f], w1c[f], acc);
        g_hpre[row * HID + t] = acc;
        __syncthreads();
    }
}

// ===========================================================================
// Stage B: radius neighbors (unchanged)
// ===========================================================================
#define NB_THREADS 256
#define NB_CPW     4
#define NB_CPB     32
#define NB_TILE    2048
#define NB_CAP     256
#define NB_SMEM    (NB_TILE * 16 + NB_CPB * NB_CAP * 8)

__global__ void __launch_bounds__(NB_THREADS)
nbr_kernel(const float* __restrict__ pos)
{
    extern __shared__ char smemraw[];
    float4* ptile = (float4*)smemraw;
    unsigned long long (*cand)[NB_CAP] =
        (unsigned long long (*)[NB_CAP])(smemraw + NB_TILE * 16);

    const int lane  = threadIdx.x & 31;
    const int warp  = threadIdx.x >> 5;
    const int cbase = blockIdx.x * NB_CPB + warp * NB_CPW;
    const float R2  = (float)(0.08 * 0.08);

    float cx[NB_CPW], cy[NB_CPW], cz[NB_CPW];
    int cnt[NB_CPW];
#pragma unroll
    for (int c = 0; c < NB_CPW; c++) {
        int ci = cbase + c;
        cx[c] = g_selpos[3 * ci]; cy[c] = g_selpos[3 * ci + 1]; cz[c] = g_selpos[3 * ci + 2];
        cnt[c] = 0;
    }

    for (int tb = 0; tb < NPTS; tb += NB_TILE) {
        __syncthreads();
        for (int s = threadIdx.x; s < NB_TILE; s += NB_THREADS) {
            int g = tb + s;
            ptile[s] = make_float4(pos[3 * g], pos[3 * g + 1], pos[3 * g + 2], 0.f);
        }
        __syncthreads();
#pragma unroll
        for (int c = 0; c < NB_CPW; c++) {
            const int row = warp * NB_CPW + c;
            for (int s = lane; s < NB_TILE; s += 32) {
                float4 p = ptile[s];
                float d2 = d2_exact(cx[c] - p.x, cy[c] - p.y, cz[c] - p.z);
                bool pred = (d2 <= R2);
                unsigned m = __ballot_sync(0xffffffffu, pred);
                if (pred) {
                    int slot = cnt[c] + __popc(m & ((1u << lane) - 1u));
                    if (slot < NB_CAP)
                        cand[row][slot] =
                            ((unsigned long long)__float_as_uint(d2) << 32) |
                            (unsigned)(tb + s);
                }
                cnt[c] += __popc(m);
            }
        }
    }

#pragma unroll
    for (int c = 0; c < NB_CPW; c++) {
        const int row = warp * NB_CPW + c;
        const int ci  = cbase + c;
        const int n   = min(cnt[c], NB_CAP);
        unsigned long long* a = cand[row];
        for (int e = lane; e < NB_CAP; e += 32)
            if (e >= n) a[e] = 0xffffffffffffffffull;
        __syncwarp();
        for (int k = 2; k <= NB_CAP; k <<= 1) {
            for (int j = k >> 1; j > 0; j >>= 1) {
                __syncwarp();
                for (int e = lane; e < NB_CAP; e += 32) {
                    int p = e ^ j;
                    if (p > e) {
                        unsigned long long va = a[e], vb = a[p];
                        bool up = ((e & k) == 0);
                        if ((va > vb) == up) { a[e] = vb; a[p] = va; }
                    }
                }
            }
        }
        __syncwarp();
        const int m = min(n, KNBR);
        for (int k = lane; k < KNBR; k += 32)
            g_nbr[ci * KNBR + k] = (k < m) ? (int)(a[k] & 0xffffffffu) : -1;
        if (lane == 0) g_ncnt[ci] = m;
        __syncwarp();
    }
}

// ===========================================================================
// Stage C: PointConv + masked max (fp32x2, 8-neighbor tiles — unchanged)
// ===========================================================================
#define CV_T     8
#define CV_PAIRS 8

#define FMA2(d, a, b, c) \
    asm("fma.rn.f32x2 %0, %1, %2, %3;" : "=l"(d) : "l"(a), "l"(b), "l"(c))

__global__ void __launch_bounds__(256)
conv_kernel(const float* __restrict__ W1, const float* __restrict__ W2,
            const float* __restrict__ b2, float* __restrict__ dout, int out_size)
{
    const int half = threadIdx.x >> 7;
    const int t    = threadIdx.x & 127;
    const int barid = 1 + half;

    __shared__ __align__(16) float vbuf[2][CV_T][HID];

    unsigned long long w2p[HID / 2];
#pragma unroll
    for (int h2 = 0; h2 < HID / 2; h2++) {
        float a = W2[(2 * h2) * OUTC + t];
        float b = W2[(2 * h2 + 1) * OUTC + t];
        asm("mov.b64 %0, {%1, %2};" : "=l"(w2p[h2]) : "f"(a), "f"(b));
    }
    const float bb  = b2[t];
    const float w64 = W1[64 * HID + t], w65 = W1[65 * HID + t], w66 = W1[66 * HID + t];
    const float NEG_INF = __int_as_float(0xff800000);

    for (int cc = 0; cc < CV_PAIRS; cc++) {
        const int ci = blockIdx.x * (2 * CV_PAIRS) + half * CV_PAIRS + cc;
        const float sx = g_selpos[3 * ci], sy = g_selpos[3 * ci + 1], sz = g_selpos[3 * ci + 2];
        const float tsub = fmaf(sx, w64, fmaf(sy, w65, __fmul_rn(sz, w66)));
        const int cnt = g_ncnt[ci];
        const int* nb = &g_nbr[ci * KNBR];

        float acc = NEG_INF;
        const int nt = (cnt + CV_T - 1) / CV_T;

        float r[CV_T];
#pragma unroll
        for (int j = 0; j < CV_T; j++)
            r[j] = (j < cnt) ? __ldg(&g_hpre[nb[j] * HID + t]) : 0.f;

        for (int tb = 0; tb < nt; tb++) {
            const int k0 = tb * CV_T;
            const int kn = min(CV_T, cnt - k0);

#pragma unroll
            for (int j = 0; j < CV_T; j++)
                if (j < kn) vbuf[half][j][t] = fmaxf(r[j] - tsub, 0.f);
            asm volatile("bar.sync %0, 128;" :: "r"(barid) : "memory");

#pragma unroll
            for (int j = 0; j < CV_T; j++) {
                int kk = k0 + CV_T + j;
                if (kk < cnt) r[j] = __ldg(&g_hpre[nb[kk] * HID + t]);
            }

            unsigned long long y2[CV_T];
#pragma unroll
            for (int j = 0; j < CV_T; j++) y2[j] = 0ull;
#pragma unroll
            for (int h4 = 0; h4 < HID / 4; h4++) {
#pragma unroll
                for (int j = 0; j < CV_T; j++) {
                    ulonglong2 p = *reinterpret_cast<const ulonglong2*>(
                        &vbuf[half][j][h4 * 4]);
                    FMA2(y2[j], p.x, w2p[2 * h4],     y2[j]);
                    FMA2(y2[j], p.y, w2p[2 * h4 + 1], y2[j]);
                }
            }
#pragma unroll
            for (int j = 0; j < CV_T; j++) {
                float lo = __uint_as_float((unsigned)y2[j]);
                float hi = __uint_as_float((unsigned)(y2[j] >> 32));
                float y  = lo + hi;
                if (j < kn) acc = fmaxf(acc, y);
            }
            asm volatile("bar.sync %0, 128;" :: "r"(barid) : "memory");
        }

        const int o = ci * OUTC + t;
        if (o < out_size) dout[o] = acc + bb;
    }
}

// ===========================================================================
// Epilogue: sel_pos after the feature block; zero the rest (sel_batch = 0)
// ===========================================================================
__global__ void epilogue_kernel(float* __restrict__ dout, int out_size)
{
    const int i = blockIdx.x * blockDim.x + threadIdx.x;
    const long long idx = (long long)MSEL * OUTC + i;
    if (idx < (long long)out_size)
        dout[idx] = (i < MSEL * 3) ? g_selpos[i] : 0.0f;
}

// ===========================================================================
// Launch
// ===========================================================================
#define F1_SMEM (F1_PTS * F1_BUCKETS * 4)

extern "C" void kernel_launch(void* const* d_in, const int* in_sizes, int n_in,
                              void* d_out, int out_size)
{
    if (n_in < 7) return;
    const float* x   = (const float*)d_in[0];
    const float* pos = (const float*)d_in[1];
    // d_in[2] = batch (all zeros, int64) — unused
    const float* W1  = (const float*)d_in[3];
    const float* b1  = (const float*)d_in[4];
    const float* W2  = (const float*)d_in[5];
    const float* b2  = (const float*)d_in[6];
    float* out = (float*)d_out;

    // Prep: Morton counting-sort into 2048 spatial buckets
    zero_cells_kernel<<<(NCELL + 255) / 256, 256>>>();
    count_cells_kernel<<<(NPTS + 255) / 256, 256>>>(pos);
    scan_cells_kernel<<<1, 1024>>>();
    scatter_kernel<<<(NPTS + 255) / 256, 256>>>(pos);

    // Stage A: FPS — single CTA, min_d in 128KB SMEM
    cudaFuncSetAttribute(fps1_kernel, cudaFuncAttributeMaxDynamicSharedMemorySize, F1_SMEM);
    fps1_kernel<<<1, F1_THREADS, F1_SMEM>>>(pos);

    // Stage C0: per-point layer-1 preactivations
    hpre_kernel<<<NPTS / 64, 128>>>(x, pos, W1, b1);

    // Stage B: radius neighbors
    cudaFuncSetAttribute(nbr_kernel, cudaFuncAttributeMaxDynamicSharedMemorySize, NB_SMEM);
    nbr_kernel<<<MSEL / NB_CPB, NB_THREADS, NB_SMEM>>>(pos);

    // Stage C: PointConv + masked max (fp32x2, tiled)
    conv_kernel<<<MSEL / (2 * CV_PAIRS), 256>>>(W1, W2, b2, out, out_size);

    // Epilogue: sel_pos + zero fill
    const int tail = out_size - MSEL * OUTC;
    if (tail > 0)
        epilogue_kernel<<<(tail + 255) / 256, 256>>>(out, out_size);
}

// round 15
// speedup vs baseline: 2.0794x; 2.0794x over previous
#include <cuda_runtime.h>
#include <cuda_bf16.h>
#include <cstdint>

// ---------------------------------------------------------------------------
// Problem constants
// ---------------------------------------------------------------------------
#define NPTS   32768
#define FCH    64
#define MSEL   8192
#define KNBR   64
#define HID    128
#define OUTC   128

// ---------------------------------------------------------------------------
// Scratch (device globals; no allocation allowed)
// ---------------------------------------------------------------------------
__device__ float g_selpos[MSEL * 3];
__device__ float g_hpre[NPTS * HID];
__device__ int   g_nbr[MSEL * KNBR];
__device__ int   g_ncnt[MSEL];

// spatial-sort scratch for FPS
#define NCELL 4096                                   // 16x16x16 Morton cells
__device__ int    g_ccnt[NCELL];
__device__ int    g_coff[NCELL];
__device__ float4 g_pxyz[NPTS];                      // x,y,z, orig-idx (bit-cast)

__device__ __forceinline__ float d2_exact(float dx, float dy, float dz) {
    // Match XLA: elementwise square then add-reduce, NO fma contraction.
    return __fadd_rn(__fadd_rn(__fmul_rn(dx, dx), __fmul_rn(dy, dy)),
                     __fmul_rn(dz, dz));
}

__device__ __forceinline__ int cell_of(float x, float y, float z) {
    int cx = min(15, max(0, (int)(x * 16.0f)));
    int cy = min(15, max(0, (int)(y * 16.0f)));
    int cz = min(15, max(0, (int)(z * 16.0f)));
    int code = 0;
#pragma unroll
    for (int b = 0; b < 4; b++) {
        code |= ((cx >> b) & 1) << (3 * b);
        code |= ((cy >> b) & 1) << (3 * b + 1);
        code |= ((cz >> b) & 1) << (3 * b + 2);
    }
    return code;
}

// ===========================================================================
// Prep: Morton-cell counting sort of points
// ===========================================================================
__global__ void zero_cells_kernel() {
    int i = blockIdx.x * blockDim.x + threadIdx.x;
    if (i < NCELL) g_ccnt[i] = 0;
}

__global__ void count_cells_kernel(const float* __restrict__ pos) {
    int i = blockIdx.x * blockDim.x + threadIdx.x;
    if (i < NPTS)
        atomicAdd(&g_ccnt[cell_of(pos[3 * i], pos[3 * i + 1], pos[3 * i + 2])], 1);
}

__global__ void __launch_bounds__(1024) scan_cells_kernel() {
    __shared__ int a[NCELL], b[NCELL];
    const int tid = threadIdx.x;
    for (int s = tid; s < NCELL; s += 1024) a[s] = g_ccnt[s];
    __syncthreads();
    int* src = a; int* dst = b;
    for (int off = 1; off < NCELL; off <<= 1) {
        for (int s = tid; s < NCELL; s += 1024)
            dst[s] = src[s] + ((s >= off) ? src[s - off] : 0);
        __syncthreads();
        int* t = src; src = dst; dst = t;
    }
    for (int s = tid; s < NCELL; s += 1024)
        g_coff[s] = (s ? src[s - 1] : 0);
}

__global__ void scatter_kernel(const float* __restrict__ pos) {
    int i = blockIdx.x * blockDim.x + threadIdx.x;
    if (i >= NPTS) return;
    float x = pos[3 * i], y = pos[3 * i + 1], z = pos[3 * i + 2];
    int slot = atomicAdd(&g_coff[cell_of(x, y, z)], 1);
    g_pxyz[slot] = make_float4(x, y, z, __int_as_float(i));
}

// ===========================================================================
// Stage A: FPS — 4-CTA cluster, register-resident points + bucket pruning.
// Exchange: warp winners go DIRECTLY to CTA0 (64-slot mailbox, collect
// mbarrier count=64); CTA0 warp0 reduces and broadcasts to all CTAs' bcast
// mbarriers (count=1). No __syncthreads / CTA-level reduce in the loop.
// ===========================================================================
#define FPS_THREADS 512
#define FPS_PTS     16

__global__ void __cluster_dims__(4, 1, 1) __launch_bounds__(FPS_THREADS, 1)
fps_kernel(const float* __restrict__ pos)
{
    __shared__ __align__(8) unsigned long long cmbox[2][64][3]; // CTA0 collect slots
    __shared__ __align__(8) unsigned long long wbox[2][2];      // winner xy, z
    __shared__ __align__(8) unsigned long long cbar[2];         // collect mbarrier (CTA0)
    __shared__ __align__(8) unsigned long long bbar[2];         // bcast mbarrier

    const int tid  = threadIdx.x;
    const int rank = blockIdx.x;                    // grid = one 4-CTA cluster
    const int lane = tid & 31;
    const int warp = tid >> 5;
    const float POS_INF = __int_as_float(0x7f800000);

    if (tid == 0) {
        uint32_t c0 = (uint32_t)__cvta_generic_to_shared(&cbar[0]);
        uint32_t c1 = (uint32_t)__cvta_generic_to_shared(&cbar[1]);
        uint32_t b0 = (uint32_t)__cvta_generic_to_shared(&bbar[0]);
        uint32_t b1 = (uint32_t)__cvta_generic_to_shared(&bbar[1]);
        asm volatile("mbarrier.init.shared.b64 [%0], %1;" :: "r"(c0), "r"(64u) : "memory");
        asm volatile("mbarrier.init.shared.b64 [%0], %1;" :: "r"(c1), "r"(64u) : "memory");
        asm volatile("mbarrier.init.shared.b64 [%0], %1;" :: "r"(b0), "r"(1u)  : "memory");
        asm volatile("mbarrier.init.shared.b64 [%0], %1;" :: "r"(b1), "r"(1u)  : "memory");
    }
    __syncthreads();
    asm volatile("barrier.cluster.arrive.aligned;" ::: "memory");
    asm volatile("barrier.cluster.wait.aligned;"   ::: "memory");

    float px[FPS_PTS], py[FPS_PTS], pz[FPS_PTS], mind[FPS_PTS];
    unsigned oid[FPS_PTS];
    const int base = (rank * FPS_THREADS + tid) * FPS_PTS;

    float bxmin = POS_INF, bxmax = -POS_INF;
    float bymin = POS_INF, bymax = -POS_INF;
    float bzmin = POS_INF, bzmax = -POS_INF;
#pragma unroll
    for (int j = 0; j < FPS_PTS; j++) {
        float4 p = __ldg(&g_pxyz[base + j]);
        px[j] = p.x; py[j] = p.y; pz[j] = p.z;
        oid[j] = (unsigned)__float_as_int(p.w);
        mind[j] = POS_INF;
        bxmin = fminf(bxmin, p.x); bxmax = fmaxf(bxmax, p.x);
        bymin = fminf(bymin, p.y); bymax = fmaxf(bymax, p.y);
        bzmin = fminf(bzmin, p.z); bzmax = fmaxf(bzmax, p.z);
    }

    float wx = pos[0], wy = pos[1], wz = pos[2];
    if (rank == 0 && tid == 0) {
        g_selpos[0] = wx; g_selpos[1] = wy; g_selpos[2] = wz;
    }

    // cached bucket candidate
    float bv = POS_INF;                 // forces rescan at i=1
    unsigned boi = 0u;
    float bx = 0.f, by = 0.f, bz = 0.f;

    const uint32_t la_cm  = (uint32_t)__cvta_generic_to_shared(&cmbox[0][0][0]);
    const uint32_t la_cb  = (uint32_t)__cvta_generic_to_shared(&cbar[0]);
    const uint32_t la_wb  = (uint32_t)__cvta_generic_to_shared(&wbox[0][0]);
    const uint32_t la_bb  = (uint32_t)__cvta_generic_to_shared(&bbar[0]);

    for (int i = 1; i < MSEL; ++i) {
        const int par = i & 1;
        const unsigned ph = (unsigned)(((i - 1) >> 1) & 1);

        // ---- prune-check / exact rescan (registers only) ----
        float gx = fmaxf(fmaxf(__fsub_rd(bxmin, wx), __fsub_rd(wx, bxmax)), 0.f);
        float gy = fmaxf(fmaxf(__fsub_rd(bymin, wy), __fsub_rd(wy, bymax)), 0.f);
        float gz = fmaxf(fmaxf(__fsub_rd(bzmin, wz), __fsub_rd(wz, bzmax)), 0.f);
        float lb = __fmul_rd(
            __fadd_rd(__fadd_rd(__fmul_rd(gx, gx), __fmul_rd(gy, gy)),
                      __fmul_rd(gz, gz)),
            0.999998f);

        if (lb < bv) {
            float nbv = -1.0f; unsigned nboi = 0xffffffffu;
            float nx = 0.f, ny = 0.f, nz = 0.f;
#pragma unroll
            for (int j = 0; j < FPS_PTS; j++) {
                float dx = px[j] - wx, dy = py[j] - wy, dz = pz[j] - wz;
                float d2 = d2_exact(dx, dy, dz);
                float m  = fminf(mind[j], d2);
                mind[j]  = m;
                bool better = (m > nbv) || (m == nbv && oid[j] < nboi);
                if (better) { nbv = m; nboi = oid[j]; nx = px[j]; ny = py[j]; nz = pz[j]; }
            }
            bv = nbv; boi = nboi; bx = nx; by = ny; bz = nz;
        }

        // ---- warp reduce: max value bits, min orig idx among ties ----
        unsigned vb   = __float_as_uint(bv);
        unsigned vmax = __reduce_max_sync(0xffffffffu, vb);
        unsigned oc   = (vb == vmax) ? boi : 0xffffffffu;
        unsigned omin = __reduce_min_sync(0xffffffffu, oc);
        unsigned ball = __ballot_sync(0xffffffffu, oc == omin);
        int src = __ffs(ball) - 1;
        float kx = __shfl_sync(0xffffffffu, bx, src);
        float ky = __shfl_sync(0xffffffffu, by, src);
        float kz = __shfl_sync(0xffffffffu, bz, src);

        // ---- lane0: deliver warp winner straight to CTA0's slot ----
        if (lane == 0) {
            const int slot = (rank << 4) | warp;           // 0..63
            unsigned long long key =
                ((unsigned long long)vmax << 32) | (unsigned long long)(~omin);
            unsigned long long xy =
                ((unsigned long long)__float_as_uint(ky) << 32) | __float_as_uint(kx);
            unsigned long long zz = (unsigned long long)__float_as_uint(kz);
            uint32_t la = la_cm + (unsigned)(par * 64 + slot) * 24u;
            uint32_t ra, rb;
            asm volatile("mapa.shared::cluster.u32 %0, %1, %2;"
                         : "=r"(ra) : "r"(la), "r"(0u));
            asm volatile("st.shared::cluster.b64 [%0],    %1;" :: "r"(ra), "l"(key) : "memory");
            asm volatile("st.shared::cluster.b64 [%0+8],  %1;" :: "r"(ra), "l"(xy)  : "memory");
            asm volatile("st.shared::cluster.b64 [%0+16], %1;" :: "r"(ra), "l"(zz)  : "memory");
            uint32_t lc = la_cb + (unsigned)par * 8u;
            asm volatile("mapa.shared::cluster.u32 %0, %1, %2;"
                         : "=r"(rb) : "r"(lc), "r"(0u));
            asm volatile("mbarrier.arrive.release.cluster.shared::cluster.b64 _, [%0];"
                         :: "r"(rb) : "memory");
        }

        // ---- CTA0 warp0: aggregate 64 slots, broadcast winner ----
        if (rank == 0 && warp == 0) {
            uint32_t bar = la_cb + (unsigned)par * 8u;
            unsigned done;
            do {
                asm volatile(
                    "{\n\t.reg .pred p;\n\t"
                    "mbarrier.try_wait.parity.acquire.cluster.shared::cta.b64 p, [%1], %2, 0x989680;\n\t"
                    "selp.b32 %0, 1, 0, p;\n\t}"
                    : "=r"(done) : "r"(bar), "r"(ph) : "memory");
            } while (!done);

            unsigned long long k1 = cmbox[par][lane][0];
            unsigned long long x1 = cmbox[par][lane][1];
            unsigned long long z1 = cmbox[par][lane][2];
            unsigned long long k2 = cmbox[par][lane + 32][0];
            unsigned long long x2 = cmbox[par][lane + 32][1];
            unsigned long long z2 = cmbox[par][lane + 32][2];
            if (k2 > k1) { k1 = k2; x1 = x2; z1 = z2; }

            unsigned vb2   = (unsigned)(k1 >> 32);
            unsigned id2   = ~(unsigned)k1;
            unsigned vmax2 = __reduce_max_sync(0xffffffffu, vb2);
            unsigned oc2   = (vb2 == vmax2) ? id2 : 0xffffffffu;
            unsigned omin2 = __reduce_min_sync(0xffffffffu, oc2);
            unsigned bl2   = __ballot_sync(0xffffffffu, oc2 == omin2);
            int s2 = __ffs(bl2) - 1;
            unsigned long long WXY = __shfl_sync(0xffffffffu, x1, s2);
            unsigned long long WZZ = __shfl_sync(0xffffffffu, z1, s2);

            if (lane < 4) {
                uint32_t lw = la_wb + (unsigned)par * 16u;
                uint32_t rw, rb2;
                asm volatile("mapa.shared::cluster.u32 %0, %1, %2;"
                             : "=r"(rw) : "r"(lw), "r"((unsigned)lane));
                asm volatile("st.shared::cluster.b64 [%0],   %1;" :: "r"(rw), "l"(WXY) : "memory");
                asm volatile("st.shared::cluster.b64 [%0+8], %1;" :: "r"(rw), "l"(WZZ) : "memory");
                uint32_t lbv = la_bb + (unsigned)par * 8u;
                asm volatile("mapa.shared::cluster.u32 %0, %1, %2;"
                             : "=r"(rb2) : "r"(lbv), "r"((unsigned)lane));
                asm volatile("mbarrier.arrive.release.cluster.shared::cluster.b64 _, [%0];"
                             :: "r"(rb2) : "memory");
            }
            if (lane == 0) {
                g_selpos[3 * i]     = __uint_as_float((unsigned)WXY);
                g_selpos[3 * i + 1] = __uint_as_float((unsigned)(WXY >> 32));
                g_selpos[3 * i + 2] = __uint_as_float((unsigned)WZZ);
            }
        }

        // ---- all threads: wait local bcast, read winner ----
        {
            uint32_t bar = la_bb + (unsigned)par * 8u;
            unsigned done;
            do {
                asm volatile(
                    "{\n\t.reg .pred p;\n\t"
                    "mbarrier.try_wait.parity.acquire.cluster.shared::cta.b64 p, [%1], %2, 0x989680;\n\t"
                    "selp.b32 %0, 1, 0, p;\n\t}"
                    : "=r"(done) : "r"(bar), "r"(ph) : "memory");
            } while (!done);
        }
        unsigned long long wxy = wbox[par][0];
        unsigned long long wzz = wbox[par][1];
        wx = __uint_as_float((unsigned)wxy);
        wy = __uint_as_float((unsigned)(wxy >> 32));
        wz = __uint_as_float((unsigned)wzz);
    }

    asm volatile("barrier.cluster.arrive.aligned;" ::: "memory");
    asm volatile("barrier.cluster.wait.aligned;"   ::: "memory");
}

// ===========================================================================
// Stage C0: h_pre[j][ch] = b1[ch] + x[j,:]@W1[:64,ch] + pos[j,:]@W1[64:67,ch]
// ===========================================================================
__global__ void __launch_bounds__(128)
hpre_kernel(const float* __restrict__ x, const float* __restrict__ pos,
            const float* __restrict__ W1, const float* __restrict__ b1)
{
    const int t = threadIdx.x;
    float w1c[FCH + 3];
#pragma unroll
    for (int f = 0; f < FCH + 3; f++) w1c[f] = W1[f * HID + t];
    const float bb = b1[t];

    __shared__ float xs[FCH];
    __shared__ float ps[3];

    const int row0 = blockIdx.x * 64;
    for (int r = 0; r < 64; r++) {
        const int row = row0 + r;
        if (t < FCH) xs[t] = x[row * FCH + t];
        if (t < 3)   ps[t] = pos[row * 3 + t];
        __syncthreads();
        float acc = bb;
        acc = fmaf(ps[0], w1c[64], acc);
        acc = fmaf(ps[1], w1c[65], acc);
        acc = fmaf(ps[2], w1c[66], acc);
#pragma unroll
        for (int f = 0; f < FCH; f++) acc = fmaf(xs[f], w1c[f], acc);
        g_hpre[row * HID + t] = acc;
        __syncthreads();
    }
}

// ===========================================================================
// Stage B: radius neighbors (unchanged)
// ===========================================================================
#define NB_THREADS 256
#define NB_CPW     4
#define NB_CPB     32
#define NB_TILE    2048
#define NB_CAP     256
#define NB_SMEM    (NB_TILE * 16 + NB_CPB * NB_CAP * 8)

__global__ void __launch_bounds__(NB_THREADS)
nbr_kernel(const float* __restrict__ pos)
{
    extern __shared__ char smemraw[];
    float4* ptile = (float4*)smemraw;
    unsigned long long (*cand)[NB_CAP] =
        (unsigned long long (*)[NB_CAP])(smemraw + NB_TILE * 16);

    const int lane  = threadIdx.x & 31;
    const int warp  = threadIdx.x >> 5;
    const int cbase = blockIdx.x * NB_CPB + warp * NB_CPW;
    const float R2  = (float)(0.08 * 0.08);

    float cx[NB_CPW], cy[NB_CPW], cz[NB_CPW];
    int cnt[NB_CPW];
#pragma unroll
    for (int c = 0; c < NB_CPW; c++) {
        int ci = cbase + c;
        cx[c] = g_selpos[3 * ci]; cy[c] = g_selpos[3 * ci + 1]; cz[c] = g_selpos[3 * ci + 2];
        cnt[c] = 0;
    }

    for (int tb = 0; tb < NPTS; tb += NB_TILE) {
        __syncthreads();
        for (int s = threadIdx.x; s < NB_TILE; s += NB_THREADS) {
            int g = tb + s;
            ptile[s] = make_float4(pos[3 * g], pos[3 * g + 1], pos[3 * g + 2], 0.f);
        }
        __syncthreads();
#pragma unroll
        for (int c = 0; c < NB_CPW; c++) {
            const int row = warp * NB_CPW + c;
            for (int s = lane; s < NB_TILE; s += 32) {
                float4 p = ptile[s];
                float d2 = d2_exact(cx[c] - p.x, cy[c] - p.y, cz[c] - p.z);
                bool pred = (d2 <= R2);
                unsigned m = __ballot_sync(0xffffffffu, pred);
                if (pred) {
                    int slot = cnt[c] + __popc(m & ((1u << lane) - 1u));
                    if (slot < NB_CAP)
                        cand[row][slot] =
                            ((unsigned long long)__float_as_uint(d2) << 32) |
                            (unsigned)(tb + s);
                }
                cnt[c] += __popc(m);
            }
        }
    }

#pragma unroll
    for (int c = 0; c < NB_CPW; c++) {
        const int row = warp * NB_CPW + c;
        const int ci  = cbase + c;
        const int n   = min(cnt[c], NB_CAP);
        unsigned long long* a = cand[row];
        for (int e = lane; e < NB_CAP; e += 32)
            if (e >= n) a[e] = 0xffffffffffffffffull;
        __syncwarp();
        for (int k = 2; k <= NB_CAP; k <<= 1) {
            for (int j = k >> 1; j > 0; j >>= 1) {
                __syncwarp();
                for (int e = lane; e < NB_CAP; e += 32) {
                    int p = e ^ j;
                    if (p > e) {
                        unsigned long long va = a[e], vb = a[p];
                        bool up = ((e & k) == 0);
                        if ((va > vb) == up) { a[e] = vb; a[p] = va; }
                    }
                }
            }
        }
        __syncwarp();
        const int m = min(n, KNBR);
        for (int k = lane; k < KNBR; k += 32)
            g_nbr[ci * KNBR + k] = (k < m) ? (int)(a[k] & 0xffffffffu) : -1;
        if (lane == 0) g_ncnt[ci] = m;
        __syncwarp();
    }
}

// ===========================================================================
// Stage C: PointConv + masked max (fp32x2, 8-neighbor tiles — unchanged)
// ===========================================================================
#define CV_T     8
#define CV_PAIRS 8

#define FMA2(d, a, b, c) \
    asm("fma.rn.f32x2 %0, %1, %2, %3;" : "=l"(d) : "l"(a), "l"(b), "l"(c))

__global__ void __launch_bounds__(256)
conv_kernel(const float* __restrict__ W1, const float* __restrict__ W2,
            const float* __restrict__ b2, float* __restrict__ dout, int out_size)
{
    const int half = threadIdx.x >> 7;
    const int t    = threadIdx.x & 127;
    const int barid = 1 + half;

    __shared__ __align__(16) float vbuf[2][CV_T][HID];

    unsigned long long w2p[HID / 2];
#pragma unroll
    for (int h2 = 0; h2 < HID / 2; h2++) {
        float a = W2[(2 * h2) * OUTC + t];
        float b = W2[(2 * h2 + 1) * OUTC + t];
        asm("mov.b64 %0, {%1, %2};" : "=l"(w2p[h2]) : "f"(a), "f"(b));
    }
    const float bb  = b2[t];
    const float w64 = W1[64 * HID + t], w65 = W1[65 * HID + t], w66 = W1[66 * HID + t];
    const float NEG_INF = __int_as_float(0xff800000);

    for (int cc = 0; cc < CV_PAIRS; cc++) {
        const int ci = blockIdx.x * (2 * CV_PAIRS) + half * CV_PAIRS + cc;
        const float sx = g_selpos[3 * ci], sy = g_selpos[3 * ci + 1], sz = g_selpos[3 * ci + 2];
        const float tsub = fmaf(sx, w64, fmaf(sy, w65, __fmul_rn(sz, w66)));
        const int cnt = g_ncnt[ci];
        const int* nb = &g_nbr[ci * KNBR];

        float acc = NEG_INF;
        const int nt = (cnt + CV_T - 1) / CV_T;

        float r[CV_T];
#pragma unroll
        for (int j = 0; j < CV_T; j++)
            r[j] = (j < cnt) ? __ldg(&g_hpre[nb[j] * HID + t]) : 0.f;

        for (int tb = 0; tb < nt; tb++) {
            const int k0 = tb * CV_T;
            const int kn = min(CV_T, cnt - k0);

#pragma unroll
            for (int j = 0; j < CV_T; j++)
                if (j < kn) vbuf[half][j][t] = fmaxf(r[j] - tsub, 0.f);
            asm volatile("bar.sync %0, 128;" :: "r"(barid) : "memory");

#pragma unroll
            for (int j = 0; j < CV_T; j++) {
                int kk = k0 + CV_T + j;
                if (kk < cnt) r[j] = __ldg(&g_hpre[nb[kk] * HID + t]);
            }

            unsigned long long y2[CV_T];
#pragma unroll
            for (int j = 0; j < CV_T; j++) y2[j] = 0ull;
#pragma unroll
            for (int h4 = 0; h4 < HID / 4; h4++) {
#pragma unroll
                for (int j = 0; j < CV_T; j++) {
                    ulonglong2 p = *reinterpret_cast<const ulonglong2*>(
                        &vbuf[half][j][h4 * 4]);
                    FMA2(y2[j], p.x, w2p[2 * h4],     y2[j]);
                    FMA2(y2[j], p.y, w2p[2 * h4 + 1], y2[j]);
                }
            }
#pragma unroll
            for (int j = 0; j < CV_T; j++) {
                float lo = __uint_as_float((unsigned)y2[j]);
                float hi = __uint_as_float((unsigned)(y2[j] >> 32));
                float y  = lo + hi;
                if (j < kn) acc = fmaxf(acc, y);
            }
            asm volatile("bar.sync %0, 128;" :: "r"(barid) : "memory");
        }

        const int o = ci * OUTC + t;
        if (o < out_size) dout[o] = acc + bb;
    }
}

// ===========================================================================
// Epilogue: sel_pos after the feature block; zero the rest (sel_batch = 0)
// ===========================================================================
__global__ void epilogue_kernel(float* __restrict__ dout, int out_size)
{
    const int i = blockIdx.x * blockDim.x + threadIdx.x;
    const long long idx = (long long)MSEL * OUTC + i;
    if (idx < (long long)out_size)
        dout[idx] = (i < MSEL * 3) ? g_selpos[i] : 0.0f;
}

// ===========================================================================
// Launch
// ===========================================================================
extern "C" void kernel_launch(void* const* d_in, const int* in_sizes, int n_in,
                              void* d_out, int out_size)
{
    if (n_in < 7) return;
    const float* x   = (const float*)d_in[0];
    const float* pos = (const float*)d_in[1];
    // d_in[2] = batch (all zeros, int64) — unused
    const float* W1  = (const float*)d_in[3];
    const float* b1  = (const float*)d_in[4];
    const float* W2  = (const float*)d_in[5];
    const float* b2  = (const float*)d_in[6];
    float* out = (float*)d_out;

    // Prep: Morton counting-sort into 2048 spatial buckets
    zero_cells_kernel<<<(NCELL + 255) / 256, 256>>>();
    count_cells_kernel<<<(NPTS + 255) / 256, 256>>>(pos);
    scan_cells_kernel<<<1, 1024>>>();
    scatter_kernel<<<(NPTS + 255) / 256, 256>>>(pos);

    // Stage A: FPS (one 4-CTA cluster, aggregator exchange)
    fps_kernel<<<4, FPS_THREADS>>>(pos);

    // Stage C0: per-point layer-1 preactivations
    hpre_kernel<<<NPTS / 64, 128>>>(x, pos, W1, b1);

    // Stage B: radius neighbors
    cudaFuncSetAttribute(nbr_kernel, cudaFuncAttributeMaxDynamicSharedMemorySize, NB_SMEM);
    nbr_kernel<<<MSEL / NB_CPB, NB_THREADS, NB_SMEM>>>(pos);

    // Stage C: PointConv + masked max (fp32x2, tiled)
    conv_kernel<<<MSEL / (2 * CV_PAIRS), 256>>>(W1, W2, b2, out, out_size);

    // Epilogue: sel_pos + zero fill
    const int tail = out_size - MSEL * OUTC;
    if (tail > 0)
        epilogue_kernel<<<(tail + 255) / 256, 256>>>(out, out_size);
}